// round 9
// baseline (speedup 1.0000x reference)
#include <cuda_runtime.h>
#include <cstdint>

// Problem dims (fixed by the dataset problem)
#define RB 64      // batch
#define RT 512     // time steps
#define RI 128     // input dim
#define RH 512     // hidden dim
#define RO 64      // output dim

// ---------------------------------------------------------------------------
// Device scratch (allocation-free rule: __device__ globals)
// ---------------------------------------------------------------------------
__device__ float g_winT[RI * RH];                // W_in transposed: [I][H]
__device__ float g_xproj[(size_t)RB * RT * RH];  // [B][T][H] input projections
__device__ float g_hhist[(size_t)RB * RT * RH];  // [B][T][H] hidden states

// Packed fp32x2 helpers (Blackwell FFMA2 — ptxas never emits this from C++)
#define PK2(dst, lo, hi) \
    asm("mov.b64 %0, {%1, %2};" : "=l"(dst) : "f"(lo), "f"(hi))
#define UPK2(lo, hi, src) \
    asm("mov.b64 {%0, %1}, %2;" : "=f"(lo), "=f"(hi) : "l"(src))
#define FMA2(acc, a, b) \
    asm("fma.rn.f32x2 %0, %1, %2, %0;" : "+l"(acc) : "l"(a), "l"(b))

// Cluster-scope mbarrier ops
#define MBAR_INIT(addr, cnt) \
    asm volatile("mbarrier.init.shared.b64 [%0], %1;" :: "r"(addr), "r"(cnt) : "memory")
// Remote (or self) arrive with cluster-release semantics via mapa'd address
#define MBAR_ARRIVE_REMOTE(addr) \
    asm volatile("mbarrier.arrive.release.cluster.shared::cluster.b64 _, [%0];" \
                 :: "r"(addr) : "memory")
// Poll-wait on local mbarrier with cluster-acquire (orders remote DSMEM writes)
#define MBAR_WAITC(addr, par) do {                                            \
    uint32_t _done = 0;                                                       \
    do {                                                                      \
        asm volatile(                                                         \
            "{\n\t.reg .pred p;\n\t"                                          \
            "mbarrier.try_wait.parity.acquire.cluster.shared::cta.b64 p, [%1], %2;\n\t" \
            "selp.b32 %0, 1, 0, p;\n\t}"                                      \
            : "=r"(_done) : "r"(addr), "r"((uint32_t)(par)) : "memory");      \
    } while (!_done);                                                         \
} while (0)

// ---------------------------------------------------------------------------
// Kernel 0: transpose W_in [H][I] -> g_winT [I][H]  (tiny, 256 KB)
// ---------------------------------------------------------------------------
__global__ void k0_transpose(const float* __restrict__ W_in) {
    int idx = blockIdx.x * blockDim.x + threadIdx.x;   // 0 .. I*H-1
    int h = idx & (RH - 1);
    int i = idx >> 9;           // idx / RH
    g_winT[i * RH + h] = W_in[h * RI + i];
}

// ---------------------------------------------------------------------------
// Kernel 1: x_proj[b][t][h] = sum_i inputs[b][t][i] * W_in[h][i]
// Tiled fp32 GEMM: CTA = 64 rows (b,t) x 128 h-cols, K = 128 (one pass).
// ---------------------------------------------------------------------------
#define K1_SMEM_BYTES ((64 * 128 + 128 * 132) * 4)

__global__ void k1_xproj(const float* __restrict__ inp) {
    extern __shared__ float sm[];
    float* As = sm;                  // [64][128]
    float* Ws = sm + 64 * 128;       // [128][132] (padded, k-major)
    const int row0 = blockIdx.x * 64;   // row in [B*T)
    const int hc   = blockIdx.y * 128;  // h col base
    const int tid  = threadIdx.x;

    for (int idx = tid; idx < 64 * 128; idx += 256)
        As[idx] = inp[(size_t)row0 * RI + idx];     // rows contiguous
    for (int idx = tid; idx < 128 * 128; idx += 256) {
        int i = idx >> 7, h = idx & 127;
        Ws[i * 132 + h] = g_winT[i * RH + hc + h];
    }
    __syncthreads();

    const int colg = tid & 31;     // 32 col groups (h = colg + 32*j)
    const int warp = tid >> 5;     // 8 row groups (r = warp + 8*jr)
    float acc[8][4];
#pragma unroll
    for (int a = 0; a < 8; a++)
#pragma unroll
        for (int b = 0; b < 4; b++) acc[a][b] = 0.f;

#pragma unroll 4
    for (int k = 0; k < 128; k++) {
        float w[4], a[8];
#pragma unroll
        for (int j = 0; j < 4; j++) w[j] = Ws[k * 132 + colg + 32 * j];
#pragma unroll
        for (int jr = 0; jr < 8; jr++) a[jr] = As[(warp + 8 * jr) * 128 + k];
#pragma unroll
        for (int jr = 0; jr < 8; jr++)
#pragma unroll
            for (int j = 0; j < 4; j++) acc[jr][j] += a[jr] * w[j];
    }

#pragma unroll
    for (int jr = 0; jr < 8; jr++)
#pragma unroll
        for (int j = 0; j < 4; j++)
            g_xproj[(size_t)(row0 + warp + 8 * jr) * RH + hc + colg + 32 * j] = acc[jr][j];
}

// ---------------------------------------------------------------------------
// Kernel 2: recurrent scan — fine-grained mbarrier producer/consumer cluster.
// Grid: 128 CTAs = 16 clusters x 8 CTAs. Cluster owns 4 batch rows; CTA rank
// r owns hidden cols [64r,64r+64); W register-resident (ulonglong2 wr[32]).
//
// Chunk flow: warp w's GEMM k-range [64w,64w+64) == rank w's chunk. Per CTA:
//   full[8] mbarriers (count=64): producer rank w's 64 epilogue threads each
//     push one float4 (st.shared::cluster.v4) then arrive.release.cluster.
//     Consumer warp w waits full[w] parity (t-1)&1 before its GEMM.
//   empty (count=8): warp w acks CTA rank w after writing its partials
//     (reads of chunk w complete). Producer waits acks(t) (parity t&1)
//     before pushing h(t) — WAR protection + phase-substitution guard.
// red partials double-buffered by t-parity -> only ONE __syncthreads/step.
// No barrier.cluster in the loop. Epilogue: 64 threads, one col x 4 batch
// each -> push float4 straight from registers.
//
// EXIT SAFETY (the R8 crash): final-step acks are skipped (t < RT-1), so
// every remote arrive is consumed by a matching wait before any CTA can
// finish, and a trailing barrier.cluster keeps all CTAs alive until the
// cluster is quiescent. No remote op can target an exited CTA.
// ---------------------------------------------------------------------------
#define K2_WSTRIDE 72                           // floats per k-row of W staging (pad)
#define K2_HB_OFF  (512 * K2_WSTRIDE)           // 36864 floats
#define K2_RED_OFF (K2_HB_OFF + 2 * 512 * 4)    // 40960: red[2][16][4][64]
#define K2_BS_OFF  (K2_RED_OFF + 2 * 16 * 256)  // 49152: bias[64]
#define K2_MB_OFF  (K2_BS_OFF + 64)             // 49216: mbars (8 full + 1 empty)
#define K2_SMEM_FLOATS (K2_MB_OFF + 20)
#define K2_SMEM_BYTES (K2_SMEM_FLOATS * 4)      // 196944 B

__global__ void __launch_bounds__(256, 1)
k2_rnn(const float* __restrict__ hidden,
       const float* __restrict__ W_rec,
       const float* __restrict__ bvec) {
    extern __shared__ float sm[];
    float* Wl  = sm;                    // [512][72]      W staging (init only)
    float* hb  = sm + K2_HB_OFF;        // [2][512][4]    h, k-major, b minor
    float* red = sm + K2_RED_OFF;       // [2][16][4][64] partials, parity-buffered
    float* bs  = sm + K2_BS_OFF;        // [64] bias slice

    const int tid  = threadIdx.x;
    const unsigned rank = blockIdx.x & 7;     // == %cluster_ctarank for (8,1,1)
    const int b0  = (blockIdx.x >> 3) * 4;    // batch base for this cluster
    const int c0g = rank * 64;                // global col base for this CTA

    // Stage W_rec slice into SMEM, transposing to k-major (one-time)
    for (int idx = tid; idx < 64 * 512; idx += 256) {
        int c = idx >> 9, k = idx & 511;
        Wl[k * K2_WSTRIDE + c] = W_rec[(size_t)(c0g + c) * RH + k];
    }
    if (tid < 64) bs[tid] = bvec[c0g + tid];
    // Initial hidden -> slot 0
    for (int idx = tid; idx < 2048; idx += 256) {
        int b = idx & 3, k = idx >> 2;
        hb[k * 4 + b] = hidden[(b0 + b) * RH + k];
    }

    uint32_t smem_u32;
    asm("{ .reg .u64 t; cvta.to.shared.u64 t, %1; cvt.u32.u64 %0, t; }"
        : "=r"(smem_u32) : "l"(sm));
    const uint32_t hb_base = smem_u32 + (uint32_t)(K2_HB_OFF * 4);
    const uint32_t mb_base = smem_u32 + (uint32_t)(K2_MB_OFF * 4);

    // mbarrier init: full[w] count=64 (producer's 64 pushing threads),
    // empty count=8 (one ack per consumer CTA)
    if (tid == 0) {
#pragma unroll
        for (int w = 0; w < 8; w++) MBAR_INIT(mb_base + w * 8, 64);
        MBAR_INIT(mb_base + 64, 8);
    }
    __syncthreads();

    const int colg   = tid & 15;
    const int kslice = tid >> 4;
    const int kbase  = kslice * 32;
    const int wid    = tid >> 5;     // warp id == chunk/rank this warp consumes

    // ---- pull this thread's W tile into registers (64 pairs = 128 regs) ----
    ulonglong2 wr[32];
#pragma unroll
    for (int kk = 0; kk < 32; kk++)
        wr[kk] = *reinterpret_cast<const ulonglong2*>(
            Wl + (kbase + kk) * K2_WSTRIDE + colg * 4);   // (w0,w1),(w2,w3)

    // Hoisted addresses
    const uint32_t fw_addr = mb_base + (uint32_t)(wid * 8);   // my warp's full mbar
    uint32_t ack_addr;   // CTA rank <wid>'s empty mbar
    asm("mapa.shared::cluster.u32 %0, %1, %2;"
        : "=r"(ack_addr) : "r"(mb_base + 64u), "r"(wid));
    uint32_t pb[8], pf[8];   // push data bases + full mbars at each dest
#pragma unroll
    for (int r = 0; r < 8; r++) {
        asm("mapa.shared::cluster.u32 %0, %1, %2;" : "=r"(pb[r]) : "r"(hb_base), "r"(r));
        asm("mapa.shared::cluster.u32 %0, %1, %2;"
            : "=r"(pf[r]) : "r"(mb_base + (uint32_t)(rank * 8)), "r"(r));
    }
    const uint32_t emp_addr = mb_base + 64;

    // Epilogue (tid<64): one col, all 4 batch rows
    const int uc  = tid;              // col (valid when tid<64)
    const int gcu = c0g + (tid & 63);
    const float bias = bs[tid & 63];
    const float* xp_p = g_xproj + (size_t)b0 * RT * RH + gcu;
    float*       hh_p = g_hhist + (size_t)b0 * RT * RH + gcu;
    const uint32_t choff = (uint32_t)(gcu * 16);   // byte offset of col's float4

    float4* red4 = reinterpret_cast<float4*>(red);

    // All mbarriers + initial hb visible cluster-wide before any remote op
    asm volatile("barrier.cluster.arrive.aligned;" ::: "memory");
    asm volatile("barrier.cluster.wait.aligned;"   ::: "memory");

    for (int t = 0; t < RT; t++) {
        const int par = t & 1;

        // Prefetch xp for the epilogue (independent of h — issue before wait)
        float xp0, xp1, xp2, xp3;
        if (tid < 64) {
            const size_t o = (size_t)t * RH;
            xp0 = __ldg(xp_p + o);
            xp1 = __ldg(xp_p + (size_t)RT * RH + o);
            xp2 = __ldg(xp_p + 2 * (size_t)RT * RH + o);
            xp3 = __ldg(xp_p + 3 * (size_t)RT * RH + o);
        }

        // Wait for my chunk (rank <wid>'s push of h(t-1)); phase t-1
        if (t > 0) MBAR_WAITC(fw_addr, (t - 1) & 1);

        // ---- A) GEMM from register-resident W on hb[par] chunk wid ----
        const float4* h4 = reinterpret_cast<const float4*>(hb + par * 2048 + kbase * 4);
        uint64_t a0p0 = 0, a0p1 = 0, a1p0 = 0, a1p1 = 0;
        uint64_t a2p0 = 0, a2p1 = 0, a3p0 = 0, a3p1 = 0;
#pragma unroll
        for (int kk = 0; kk < 32; kk++) {
            const float4 hv = h4[kk];          // broadcast LDS.128
            uint64_t hd0, hd1, hd2, hd3;
            PK2(hd0, hv.x, hv.x);
            PK2(hd1, hv.y, hv.y);
            PK2(hd2, hv.z, hv.z);
            PK2(hd3, hv.w, hv.w);
            FMA2(a0p0, hd0, wr[kk].x); FMA2(a0p1, hd0, wr[kk].y);
            FMA2(a1p0, hd1, wr[kk].x); FMA2(a1p1, hd1, wr[kk].y);
            FMA2(a2p0, hd2, wr[kk].x); FMA2(a2p1, hd2, wr[kk].y);
            FMA2(a3p0, hd3, wr[kk].x); FMA2(a3p1, hd3, wr[kk].y);
        }
        // partials into red[par]: red[par][kslice][b][4colg..]
        {
            float4* rp = red4 + par * 1024 + kslice * 64;
            float4 f;
            UPK2(f.x, f.y, a0p0); UPK2(f.z, f.w, a0p1);
            rp[0 * 16 + colg] = f;
            UPK2(f.x, f.y, a1p0); UPK2(f.z, f.w, a1p1);
            rp[1 * 16 + colg] = f;
            UPK2(f.x, f.y, a2p0); UPK2(f.z, f.w, a2p1);
            rp[2 * 16 + colg] = f;
            UPK2(f.x, f.y, a3p0); UPK2(f.z, f.w, a3p1);
            rp[3 * 16 + colg] = f;
        }
        // Reads of chunk <wid> are complete -> ack producer (enables its next
        // push). SKIP on the final step: nobody waits on those acks, and a
        // remote arrive racing a peer CTA's exit faults (the R8 bug).
        if (t < RT - 1) {
            __syncwarp();
            if ((tid & 31) == 0) MBAR_ARRIVE_REMOTE(ack_addr);
        }

        __syncthreads();   // partials of all warps visible to epilogue

        // ---- B/C) epilogue: 64 threads, one col x 4 b; reduce+update+push ----
        if (tid < 64) {
            const float* rp = red + par * 4096;
            float s0 = 0.f, s1 = 0.f, s2 = 0.f, s3 = 0.f;
#pragma unroll
            for (int ss = 0; ss < 16; ss++) {
                const float* q = rp + ss * 256 + uc;
                s0 += q[0];
                s1 += q[64];
                s2 += q[128];
                s3 += q[192];
            }
            float t0, t1, t2, t3;
            asm("tanh.approx.f32 %0, %1;" : "=f"(t0) : "f"(s0 + xp0 + bias));
            asm("tanh.approx.f32 %0, %1;" : "=f"(t1) : "f"(s1 + xp1 + bias));
            asm("tanh.approx.f32 %0, %1;" : "=f"(t2) : "f"(s2 + xp2 + bias));
            asm("tanh.approx.f32 %0, %1;" : "=f"(t3) : "f"(s3 + xp3 + bias));
            const float4 hold = *reinterpret_cast<const float4*>(hb + par * 2048 + gcu * 4);
            float4 v;
            v.x = 0.9f * hold.x + 0.1f * t0;
            v.y = 0.9f * hold.y + 0.1f * t1;
            v.z = 0.9f * hold.z + 0.1f * t2;
            v.w = 0.9f * hold.w + 0.1f * t3;

            // Persist h(t) for the output pass
            const size_t o = (size_t)t * RH;
            hh_p[o]                       = v.x;
            hh_p[(size_t)RT * RH + o]     = v.y;
            hh_p[2 * (size_t)RT * RH + o] = v.z;
            hh_p[3 * (size_t)RT * RH + o] = v.w;

            if (t < RT - 1) {
                // Backpressure: all 8 consumer CTAs acked reading step t
                MBAR_WAITC(emp_addr, par);
                // Push h(t) into slot (t+1)&1 at all 8 CTAs (incl. self)
                const uint32_t doff = (uint32_t)((par ^ 1) * 8192) + choff;
#pragma unroll
                for (int r = 0; r < 8; r++) {
                    asm volatile("st.shared::cluster.v4.f32 [%0], {%1,%2,%3,%4};"
                                 :: "r"(pb[r] + doff),
                                    "f"(v.x), "f"(v.y), "f"(v.z), "f"(v.w) : "memory");
                    MBAR_ARRIVE_REMOTE(pf[r]);
                }
            }
        }
    }

    // Keep every CTA alive until the whole cluster is quiescent (exit safety)
    asm volatile("barrier.cluster.arrive.aligned;" ::: "memory");
    asm volatile("barrier.cluster.wait.aligned;"   ::: "memory");
}

// ---------------------------------------------------------------------------
// Kernel 3: out[b][t][o] = sum_h hhist[b][t][h] * W_out[o][h] + b_out[o]
// CTA = 128 rows x 32 o-cols; SMEM ~99 KB -> 2 CTAs/SM, 512 CTAs.
// ---------------------------------------------------------------------------
#define K3_WS 513
#define K3_AS 65
#define K3_SMEM_BYTES ((32 * K3_WS + 128 * K3_AS) * 4)

__global__ void k3_out(const float* __restrict__ W_out,
                       const float* __restrict__ b_out,
                       float* __restrict__ out) {
    extern __shared__ float sm[];
    float* Ws = sm;                   // [32][513]
    float* As = sm + 32 * K3_WS;      // [128][65]
    const int row0 = blockIdx.x * 128;
    const int ob0  = blockIdx.y * 32;  // o col base
    const int tid  = threadIdx.x;

    for (int idx = tid; idx < 32 * 512; idx += 256) {
        int o = idx >> 9, k = idx & 511;
        Ws[o * K3_WS + k] = W_out[(size_t)(ob0 + o) * RH + k];
    }

    const int og   = tid & 15;    // o = og + 16*j, j<2
    const int rowg = tid >> 4;    // r = rowg + 16*jr, jr<8
    float acc[8][2];
#pragma unroll
    for (int a = 0; a < 8; a++) { acc[a][0] = 0.f; acc[a][1] = 0.f; }

    for (int kc = 0; kc < 8; kc++) {
        __syncthreads();
        for (int idx = tid; idx < 128 * 64; idx += 256) {
            int r = idx >> 6, k = idx & 63;
            As[r * K3_AS + k] = g_hhist[(size_t)(row0 + r) * RH + kc * 64 + k];
        }
        __syncthreads();
#pragma unroll 4
        for (int kk = 0; kk < 64; kk++) {
            const int k = kc * 64 + kk;
            float w[2], a[8];
#pragma unroll
            for (int j = 0; j < 2; j++) w[j] = Ws[(og + 16 * j) * K3_WS + k];
#pragma unroll
            for (int jr = 0; jr < 8; jr++) a[jr] = As[(rowg + 16 * jr) * K3_AS + kk];
#pragma unroll
            for (int jr = 0; jr < 8; jr++)
#pragma unroll
                for (int j = 0; j < 2; j++) acc[jr][j] += a[jr] * w[j];
        }
    }

#pragma unroll
    for (int jr = 0; jr < 8; jr++)
#pragma unroll
        for (int j = 0; j < 2; j++)
            out[(size_t)(row0 + rowg + 16 * jr) * RO + ob0 + og + 16 * j] =
                acc[jr][j] + __ldg(&b_out[ob0 + og + 16 * j]);
}

// ---------------------------------------------------------------------------
// Kernel 4: h_final[b][h] = hhist[b][T-1][h]
// ---------------------------------------------------------------------------
__global__ void k4_hfinal(float* __restrict__ outh) {
    int idx = blockIdx.x * blockDim.x + threadIdx.x;   // 0 .. B*H-1
    int b = idx >> 9, h = idx & 511;
    outh[idx] = g_hhist[(size_t)b * RT * RH + (size_t)(RT - 1) * RH + h];
}

// ---------------------------------------------------------------------------
// Launch
// ---------------------------------------------------------------------------
extern "C" void kernel_launch(void* const* d_in, const int* in_sizes, int n_in,
                              void* d_out, int out_size) {
    const float* inputs = (const float*)d_in[0];
    const float* hidden = (const float*)d_in[1];
    const float* W_in   = (const float*)d_in[2];
    const float* W_rec  = (const float*)d_in[3];
    const float* bvec   = (const float*)d_in[4];
    const float* W_out  = (const float*)d_in[5];
    const float* b_out  = (const float*)d_in[6];
    float* out = (float*)d_out;

    cudaFuncSetAttribute(k1_xproj, cudaFuncAttributeMaxDynamicSharedMemorySize, K1_SMEM_BYTES);
    cudaFuncSetAttribute(k2_rnn,   cudaFuncAttributeMaxDynamicSharedMemorySize, K2_SMEM_BYTES);
    cudaFuncSetAttribute(k3_out,   cudaFuncAttributeMaxDynamicSharedMemorySize, K3_SMEM_BYTES);

    k0_transpose<<<(RI * RH) / 256, 256>>>(W_in);
    k1_xproj<<<dim3((RB * RT) / 64, RH / 128), 256, K1_SMEM_BYTES>>>(inputs);

    cudaLaunchConfig_t cfg = {};
    cfg.gridDim  = dim3(128, 1, 1);
    cfg.blockDim = dim3(256, 1, 1);
    cfg.dynamicSmemBytes = K2_SMEM_BYTES;
    cfg.stream = 0;
    cudaLaunchAttribute attrs[1];
    attrs[0].id = cudaLaunchAttributeClusterDimension;
    attrs[0].val.clusterDim.x = 8;
    attrs[0].val.clusterDim.y = 1;
    attrs[0].val.clusterDim.z = 1;
    cfg.attrs = attrs;
    cfg.numAttrs = 1;
    cudaLaunchKernelEx(&cfg, k2_rnn, hidden, W_rec, bvec);

    k3_out<<<dim3((RB * RT) / 128, RO / 32), 256, K3_SMEM_BYTES>>>(W_out, b_out, out);

    if (out_size >= RB * RT * RO + RB * RH)
        k4_hfinal<<<(RB * RH) / 256, 256>>>(out + (size_t)RB * RT * RO);
}

// round 11
// speedup vs baseline: 1.6505x; 1.6505x over previous
#include <cuda_runtime.h>
#include <cstdint>

// Problem dims (fixed by the dataset problem)
#define RB 64      // batch
#define RT 512     // time steps
#define RI 128     // input dim
#define RH 512     // hidden dim
#define RO 64      // output dim

// ---------------------------------------------------------------------------
// Device scratch (allocation-free rule: __device__ globals)
// ---------------------------------------------------------------------------
__device__ float g_winT[RI * RH];                // W_in transposed: [I][H]
__device__ float g_xproj[(size_t)RB * RT * RH];  // [B][T][H] input projections
__device__ float g_hhist[(size_t)RB * RT * RH];  // [B][T][H] hidden states

// Packed fp32x2 helpers (Blackwell FFMA2 — ptxas never emits this from C++)
#define PK2(dst, lo, hi) \
    asm("mov.b64 %0, {%1, %2};" : "=l"(dst) : "f"(lo), "f"(hi))
#define UPK2(lo, hi, src) \
    asm("mov.b64 {%0, %1}, %2;" : "=f"(lo), "=f"(hi) : "l"(src))
#define FMA2(acc, a, b) \
    asm("fma.rn.f32x2 %0, %1, %2, %0;" : "+l"(acc) : "l"(a), "l"(b))

// Cluster-scope mbarrier ops
#define MBAR_INIT(addr, cnt) \
    asm volatile("mbarrier.init.shared.b64 [%0], %1;" :: "r"(addr), "r"(cnt) : "memory")
// Remote (or self) arrive with cluster-release semantics via mapa'd address
#define MBAR_ARRIVE_REMOTE(addr) \
    asm volatile("mbarrier.arrive.release.cluster.shared::cluster.b64 _, [%0];" \
                 :: "r"(addr) : "memory")
// Poll-wait on local mbarrier with cluster-acquire (orders remote DSMEM writes)
#define MBAR_WAITC(addr, par) do {                                            \
    uint32_t _done = 0;                                                       \
    do {                                                                      \
        asm volatile(                                                         \
            "{\n\t.reg .pred p;\n\t"                                          \
            "mbarrier.try_wait.parity.acquire.cluster.shared::cta.b64 p, [%1], %2;\n\t" \
            "selp.b32 %0, 1, 0, p;\n\t}"                                      \
            : "=r"(_done) : "r"(addr), "r"((uint32_t)(par)) : "memory");      \
    } while (!_done);                                                         \
} while (0)

// ---------------------------------------------------------------------------
// Kernel 0: transpose W_in [H][I] -> g_winT [I][H]  (tiny, 256 KB)
// ---------------------------------------------------------------------------
__global__ void k0_transpose(const float* __restrict__ W_in) {
    int idx = blockIdx.x * blockDim.x + threadIdx.x;   // 0 .. I*H-1
    int h = idx & (RH - 1);
    int i = idx >> 9;           // idx / RH
    g_winT[i * RH + h] = W_in[h * RI + i];
}

// ---------------------------------------------------------------------------
// Kernel 1: x_proj[b][t][h] = sum_i inputs[b][t][i] * W_in[h][i]
// Tiled fp32 GEMM: CTA = 64 rows (b,t) x 128 h-cols, K = 128 (one pass).
// ---------------------------------------------------------------------------
#define K1_SMEM_BYTES ((64 * 128 + 128 * 132) * 4)

__global__ void k1_xproj(const float* __restrict__ inp) {
    extern __shared__ float sm[];
    float* As = sm;                  // [64][128]
    float* Ws = sm + 64 * 128;       // [128][132] (padded, k-major)
    const int row0 = blockIdx.x * 64;   // row in [B*T)
    const int hc   = blockIdx.y * 128;  // h col base
    const int tid  = threadIdx.x;

    for (int idx = tid; idx < 64 * 128; idx += 256)
        As[idx] = inp[(size_t)row0 * RI + idx];     // rows contiguous
    for (int idx = tid; idx < 128 * 128; idx += 256) {
        int i = idx >> 7, h = idx & 127;
        Ws[i * 132 + h] = g_winT[i * RH + hc + h];
    }
    __syncthreads();

    const int colg = tid & 31;     // 32 col groups (h = colg + 32*j)
    const int warp = tid >> 5;     // 8 row groups (r = warp + 8*jr)
    float acc[8][4];
#pragma unroll
    for (int a = 0; a < 8; a++)
#pragma unroll
        for (int b = 0; b < 4; b++) acc[a][b] = 0.f;

#pragma unroll 4
    for (int k = 0; k < 128; k++) {
        float w[4], a[8];
#pragma unroll
        for (int j = 0; j < 4; j++) w[j] = Ws[k * 132 + colg + 32 * j];
#pragma unroll
        for (int jr = 0; jr < 8; jr++) a[jr] = As[(warp + 8 * jr) * 128 + k];
#pragma unroll
        for (int jr = 0; jr < 8; jr++)
#pragma unroll
            for (int j = 0; j < 4; j++) acc[jr][j] += a[jr] * w[j];
    }

#pragma unroll
    for (int jr = 0; jr < 8; jr++)
#pragma unroll
        for (int j = 0; j < 4; j++)
            g_xproj[(size_t)(row0 + warp + 8 * jr) * RH + hc + colg + 32 * j] = acc[jr][j];
}

// ---------------------------------------------------------------------------
// Kernel 2: recurrent scan — mbarrier producer/consumer with ELECTED arrives.
// Grid: 128 CTAs = 16 clusters x 8 CTAs. Cluster owns 4 batch rows; CTA rank
// r owns hidden cols [64r,64r+64); W register-resident (ulonglong2 wr[32]).
//
// vs R9 (which passed but regressed): full[w] count 64 -> 1. Producers issue
// DATA stores only (512 st.shared::cluster.v4, no per-store arrives); then
// __syncthreads; then 8 elected threads issue ONE arrive.release.cluster
// each (bar.sync gives happens-before from all pushers' stores to the
// electing thread; cumulativity carries them through release->acquire).
// Arrive traffic: 512/step -> 8/step.
//
// EXIT SAFETY (R8 lesson): final-step acks/pushes/arrives skipped; trailing
// barrier.cluster keeps CTAs alive until the cluster is quiescent.
// ---------------------------------------------------------------------------
#define K2_WSTRIDE 72                           // floats per k-row of W staging (pad)
#define K2_HB_OFF  (512 * K2_WSTRIDE)           // 36864 floats
#define K2_RED_OFF (K2_HB_OFF + 2 * 512 * 4)    // 40960: red[2][16][4][64]
#define K2_BS_OFF  (K2_RED_OFF + 2 * 16 * 256)  // 49152: bias[64]
#define K2_MB_OFF  (K2_BS_OFF + 64)             // 49216: mbars (8 full + 1 empty)
#define K2_SMEM_FLOATS (K2_MB_OFF + 20)
#define K2_SMEM_BYTES (K2_SMEM_FLOATS * 4)      // 196944 B

__global__ void __launch_bounds__(256, 1)
k2_rnn(const float* __restrict__ hidden,
       const float* __restrict__ W_rec,
       const float* __restrict__ bvec) {
    extern __shared__ float sm[];
    float* Wl  = sm;                    // [512][72]      W staging (init only)
    float* hb  = sm + K2_HB_OFF;        // [2][512][4]    h, k-major, b minor
    float* red = sm + K2_RED_OFF;       // [2][16][4][64] partials, parity-buffered
    float* bs  = sm + K2_BS_OFF;        // [64] bias slice

    const int tid  = threadIdx.x;
    const unsigned rank = blockIdx.x & 7;     // == %cluster_ctarank for (8,1,1)
    const int b0  = (blockIdx.x >> 3) * 4;    // batch base for this cluster
    const int c0g = rank * 64;                // global col base for this CTA

    // Stage W_rec slice into SMEM, transposing to k-major (one-time)
    for (int idx = tid; idx < 64 * 512; idx += 256) {
        int c = idx >> 9, k = idx & 511;
        Wl[k * K2_WSTRIDE + c] = W_rec[(size_t)(c0g + c) * RH + k];
    }
    if (tid < 64) bs[tid] = bvec[c0g + tid];
    // Initial hidden -> slot 0
    for (int idx = tid; idx < 2048; idx += 256) {
        int b = idx & 3, k = idx >> 2;
        hb[k * 4 + b] = hidden[(b0 + b) * RH + k];
    }

    uint32_t smem_u32;
    asm("{ .reg .u64 t; cvta.to.shared.u64 t, %1; cvt.u32.u64 %0, t; }"
        : "=r"(smem_u32) : "l"(sm));
    const uint32_t hb_base = smem_u32 + (uint32_t)(K2_HB_OFF * 4);
    const uint32_t mb_base = smem_u32 + (uint32_t)(K2_MB_OFF * 4);

    // mbarrier init: full[w] count=1 (single elected arrive from producer w),
    // empty count=8 (one ack per consumer CTA)
    if (tid == 0) {
#pragma unroll
        for (int w = 0; w < 8; w++) MBAR_INIT(mb_base + w * 8, 1);
        MBAR_INIT(mb_base + 64, 8);
    }
    __syncthreads();

    const int colg   = tid & 15;
    const int kslice = tid >> 4;
    const int kbase  = kslice * 32;
    const int wid    = tid >> 5;     // warp id == chunk/rank this warp consumes

    // ---- pull this thread's W tile into registers (64 pairs = 128 regs) ----
    ulonglong2 wr[32];
#pragma unroll
    for (int kk = 0; kk < 32; kk++)
        wr[kk] = *reinterpret_cast<const ulonglong2*>(
            Wl + (kbase + kk) * K2_WSTRIDE + colg * 4);   // (w0,w1),(w2,w3)

    // Hoisted addresses
    const uint32_t fw_addr = mb_base + (uint32_t)(wid * 8);   // my warp's full mbar
    uint32_t ack_addr;   // CTA rank <wid>'s empty mbar
    asm("mapa.shared::cluster.u32 %0, %1, %2;"
        : "=r"(ack_addr) : "r"(mb_base + 64u), "r"(wid));
    uint32_t pb[8];      // push data bases at each dest (constant-indexed)
#pragma unroll
    for (int r = 0; r < 8; r++)
        asm("mapa.shared::cluster.u32 %0, %1, %2;" : "=r"(pb[r]) : "r"(hb_base), "r"(r));
    // Elected-arrive target: dest CTA <tid>'s full[rank]  (tid<8 only)
    uint32_t el_addr = 0;
    if (tid < 8)
        asm("mapa.shared::cluster.u32 %0, %1, %2;"
            : "=r"(el_addr) : "r"(mb_base + (uint32_t)(rank * 8)), "r"(tid));
    const uint32_t emp_addr = mb_base + 64;

    // Epilogue (tid<64): one col, all 4 batch rows
    const int uc  = tid;              // col (valid when tid<64)
    const int gcu = c0g + (tid & 63);
    const float bias = bs[tid & 63];
    const float* xp_p = g_xproj + (size_t)b0 * RT * RH + gcu;
    float*       hh_p = g_hhist + (size_t)b0 * RT * RH + gcu;
    const uint32_t choff = (uint32_t)(gcu * 16);   // byte offset of col's float4

    float4* red4 = reinterpret_cast<float4*>(red);

    // All mbarriers + initial hb visible cluster-wide before any remote op
    asm volatile("barrier.cluster.arrive.aligned;" ::: "memory");
    asm volatile("barrier.cluster.wait.aligned;"   ::: "memory");

    for (int t = 0; t < RT; t++) {
        const int par = t & 1;

        // Prefetch xp for the epilogue (independent of h — issue before wait)
        float xp0, xp1, xp2, xp3;
        if (tid < 64) {
            const size_t o = (size_t)t * RH;
            xp0 = __ldg(xp_p + o);
            xp1 = __ldg(xp_p + (size_t)RT * RH + o);
            xp2 = __ldg(xp_p + 2 * (size_t)RT * RH + o);
            xp3 = __ldg(xp_p + 3 * (size_t)RT * RH + o);
        }

        // Wait for my chunk (rank <wid>'s push of h(t-1)); phase t-1
        if (t > 0) MBAR_WAITC(fw_addr, (t - 1) & 1);

        // ---- A) GEMM from register-resident W on hb[par] chunk wid ----
        const float4* h4 = reinterpret_cast<const float4*>(hb + par * 2048 + kbase * 4);
        uint64_t a0p0 = 0, a0p1 = 0, a1p0 = 0, a1p1 = 0;
        uint64_t a2p0 = 0, a2p1 = 0, a3p0 = 0, a3p1 = 0;
#pragma unroll
        for (int kk = 0; kk < 32; kk++) {
            const float4 hv = h4[kk];          // broadcast LDS.128
            uint64_t hd0, hd1, hd2, hd3;
            PK2(hd0, hv.x, hv.x);
            PK2(hd1, hv.y, hv.y);
            PK2(hd2, hv.z, hv.z);
            PK2(hd3, hv.w, hv.w);
            FMA2(a0p0, hd0, wr[kk].x); FMA2(a0p1, hd0, wr[kk].y);
            FMA2(a1p0, hd1, wr[kk].x); FMA2(a1p1, hd1, wr[kk].y);
            FMA2(a2p0, hd2, wr[kk].x); FMA2(a2p1, hd2, wr[kk].y);
            FMA2(a3p0, hd3, wr[kk].x); FMA2(a3p1, hd3, wr[kk].y);
        }
        // partials into red[par]: red[par][kslice][b][4colg..]
        {
            float4* rp = red4 + par * 1024 + kslice * 64;
            float4 f;
            UPK2(f.x, f.y, a0p0); UPK2(f.z, f.w, a0p1);
            rp[0 * 16 + colg] = f;
            UPK2(f.x, f.y, a1p0); UPK2(f.z, f.w, a1p1);
            rp[1 * 16 + colg] = f;
            UPK2(f.x, f.y, a2p0); UPK2(f.z, f.w, a2p1);
            rp[2 * 16 + colg] = f;
            UPK2(f.x, f.y, a3p0); UPK2(f.z, f.w, a3p1);
            rp[3 * 16 + colg] = f;
        }
        // Reads of chunk <wid> complete -> ack producer (skip final step)
        if (t < RT - 1) {
            __syncwarp();
            if ((tid & 31) == 0) MBAR_ARRIVE_REMOTE(ack_addr);
        }

        __syncthreads();   // partials of all warps visible to epilogue

        // ---- B/C) epilogue: 64 threads, one col x 4 b; reduce+update+push ----
        if (tid < 64) {
            const float* rp = red + par * 4096;
            float s0 = 0.f, s1 = 0.f, s2 = 0.f, s3 = 0.f;
#pragma unroll
            for (int ss = 0; ss < 16; ss++) {
                const float* q = rp + ss * 256 + uc;
                s0 += q[0];
                s1 += q[64];
                s2 += q[128];
                s3 += q[192];
            }
            float t0, t1, t2, t3;
            asm("tanh.approx.f32 %0, %1;" : "=f"(t0) : "f"(s0 + xp0 + bias));
            asm("tanh.approx.f32 %0, %1;" : "=f"(t1) : "f"(s1 + xp1 + bias));
            asm("tanh.approx.f32 %0, %1;" : "=f"(t2) : "f"(s2 + xp2 + bias));
            asm("tanh.approx.f32 %0, %1;" : "=f"(t3) : "f"(s3 + xp3 + bias));
            const float4 hold = *reinterpret_cast<const float4*>(hb + par * 2048 + gcu * 4);
            float4 v;
            v.x = 0.9f * hold.x + 0.1f * t0;
            v.y = 0.9f * hold.y + 0.1f * t1;
            v.z = 0.9f * hold.z + 0.1f * t2;
            v.w = 0.9f * hold.w + 0.1f * t3;

            if (t < RT - 1) {
                // Backpressure: all 8 consumer CTAs acked reading step t
                MBAR_WAITC(emp_addr, par);
                // Push h(t) into slot (t+1)&1 at all 8 CTAs — DATA ONLY
                const uint32_t doff = (uint32_t)((par ^ 1) * 8192) + choff;
#pragma unroll
                for (int r = 0; r < 8; r++)
                    asm volatile("st.shared::cluster.v4.f32 [%0], {%1,%2,%3,%4};"
                                 :: "r"(pb[r] + doff),
                                    "f"(v.x), "f"(v.y), "f"(v.z), "f"(v.w) : "memory");
            }

            // Persist h(t) for the output pass (off the critical path)
            const size_t o = (size_t)t * RH;
            hh_p[o]                       = v.x;
            hh_p[(size_t)RT * RH + o]     = v.y;
            hh_p[2 * (size_t)RT * RH + o] = v.z;
            hh_p[3 * (size_t)RT * RH + o] = v.w;
        }

        if (t < RT - 1) {
            __syncthreads();   // all pushers done (happens-before for elected arrive)
            // 8 elected threads: one release-arrive per destination CTA
            if (tid < 8) MBAR_ARRIVE_REMOTE(el_addr);
        }
    }

    // Keep every CTA alive until the whole cluster is quiescent (exit safety)
    asm volatile("barrier.cluster.arrive.aligned;" ::: "memory");
    asm volatile("barrier.cluster.wait.aligned;"   ::: "memory");
}

// ---------------------------------------------------------------------------
// Kernel 3: out[b][t][o] = sum_h hhist[b][t][h] * W_out[o][h] + b_out[o]
// CTA = 128 rows x 32 o-cols; SMEM ~99 KB -> 2 CTAs/SM, 512 CTAs.
// ---------------------------------------------------------------------------
#define K3_WS 513
#define K3_AS 65
#define K3_SMEM_BYTES ((32 * K3_WS + 128 * K3_AS) * 4)

__global__ void k3_out(const float* __restrict__ W_out,
                       const float* __restrict__ b_out,
                       float* __restrict__ out) {
    extern __shared__ float sm[];
    float* Ws = sm;                   // [32][513]
    float* As = sm + 32 * K3_WS;      // [128][65]
    const int row0 = blockIdx.x * 128;
    const int ob0  = blockIdx.y * 32;  // o col base
    const int tid  = threadIdx.x;

    for (int idx = tid; idx < 32 * 512; idx += 256) {
        int o = idx >> 9, k = idx & 511;
        Ws[o * K3_WS + k] = W_out[(size_t)(ob0 + o) * RH + k];
    }

    const int og   = tid & 15;    // o = og + 16*j, j<2
    const int rowg = tid >> 4;    // r = rowg + 16*jr, jr<8
    float acc[8][2];
#pragma unroll
    for (int a = 0; a < 8; a++) { acc[a][0] = 0.f; acc[a][1] = 0.f; }

    for (int kc = 0; kc < 8; kc++) {
        __syncthreads();
        for (int idx = tid; idx < 128 * 64; idx += 256) {
            int r = idx >> 6, k = idx & 63;
            As[r * K3_AS + k] = g_hhist[(size_t)(row0 + r) * RH + kc * 64 + k];
        }
        __syncthreads();
#pragma unroll 4
        for (int kk = 0; kk < 64; kk++) {
            const int k = kc * 64 + kk;
            float w[2], a[8];
#pragma unroll
            for (int j = 0; j < 2; j++) w[j] = Ws[(og + 16 * j) * K3_WS + k];
#pragma unroll
            for (int jr = 0; jr < 8; jr++) a[jr] = As[(rowg + 16 * jr) * K3_AS + kk];
#pragma unroll
            for (int jr = 0; jr < 8; jr++)
#pragma unroll
                for (int j = 0; j < 2; j++) acc[jr][j] += a[jr] * w[j];
        }
    }

#pragma unroll
    for (int jr = 0; jr < 8; jr++)
#pragma unroll
        for (int j = 0; j < 2; j++)
            out[(size_t)(row0 + rowg + 16 * jr) * RO + ob0 + og + 16 * j] =
                acc[jr][j] + __ldg(&b_out[ob0 + og + 16 * j]);
}

// ---------------------------------------------------------------------------
// Kernel 4: h_final[b][h] = hhist[b][T-1][h]
// ---------------------------------------------------------------------------
__global__ void k4_hfinal(float* __restrict__ outh) {
    int idx = blockIdx.x * blockDim.x + threadIdx.x;   // 0 .. B*H-1
    int b = idx >> 9, h = idx & 511;
    outh[idx] = g_hhist[(size_t)b * RT * RH + (size_t)(RT - 1) * RH + h];
}

// ---------------------------------------------------------------------------
// Launch
// ---------------------------------------------------------------------------
extern "C" void kernel_launch(void* const* d_in, const int* in_sizes, int n_in,
                              void* d_out, int out_size) {
    const float* inputs = (const float*)d_in[0];
    const float* hidden = (const float*)d_in[1];
    const float* W_in   = (const float*)d_in[2];
    const float* W_rec  = (const float*)d_in[3];
    const float* bvec   = (const float*)d_in[4];
    const float* W_out  = (const float*)d_in[5];
    const float* b_out  = (const float*)d_in[6];
    float* out = (float*)d_out;

    cudaFuncSetAttribute(k1_xproj, cudaFuncAttributeMaxDynamicSharedMemorySize, K1_SMEM_BYTES);
    cudaFuncSetAttribute(k2_rnn,   cudaFuncAttributeMaxDynamicSharedMemorySize, K2_SMEM_BYTES);
    cudaFuncSetAttribute(k3_out,   cudaFuncAttributeMaxDynamicSharedMemorySize, K3_SMEM_BYTES);

    k0_transpose<<<(RI * RH) / 256, 256>>>(W_in);
    k1_xproj<<<dim3((RB * RT) / 64, RH / 128), 256, K1_SMEM_BYTES>>>(inputs);

    cudaLaunchConfig_t cfg = {};
    cfg.gridDim  = dim3(128, 1, 1);
    cfg.blockDim = dim3(256, 1, 1);
    cfg.dynamicSmemBytes = K2_SMEM_BYTES;
    cfg.stream = 0;
    cudaLaunchAttribute attrs[1];
    attrs[0].id = cudaLaunchAttributeClusterDimension;
    attrs[0].val.clusterDim.x = 8;
    attrs[0].val.clusterDim.y = 1;
    attrs[0].val.clusterDim.z = 1;
    cfg.attrs = attrs;
    cfg.numAttrs = 1;
    cudaLaunchKernelEx(&cfg, k2_rnn, hidden, W_rec, bvec);

    k3_out<<<dim3((RB * RT) / 128, RO / 32), 256, K3_SMEM_BYTES>>>(W_out, b_out, out);

    if (out_size >= RB * RT * RO + RB * RH)
        k4_hfinal<<<(RB * RH) / 256, 256>>>(out + (size_t)RB * RT * RO);
}

// round 14
// speedup vs baseline: 2.3924x; 1.4495x over previous
#include <cuda_runtime.h>
#include <cstdint>

// Problem dims (fixed by the dataset problem)
#define RB 64      // batch
#define RT 512     // time steps
#define RI 128     // input dim
#define RH 512     // hidden dim
#define RO 64      // output dim

// ---------------------------------------------------------------------------
// Device scratch (allocation-free rule: __device__ globals)
// ---------------------------------------------------------------------------
__device__ float g_winT[RI * RH];                // W_in transposed: [I][H]
__device__ float g_xproj[(size_t)RB * RT * RH];  // [B][T][H] input projections
__device__ float g_hhist[(size_t)RB * RT * RH];  // [B][T][H] hidden states

// Packed fp32x2 helpers (Blackwell FFMA2 — ptxas never emits this from C++)
#define PK2(dst, lo, hi) \
    asm("mov.b64 %0, {%1, %2};" : "=l"(dst) : "f"(lo), "f"(hi))
#define UPK2(lo, hi, src) \
    asm("mov.b64 {%0, %1}, %2;" : "=f"(lo), "=f"(hi) : "l"(src))
#define FMA2(acc, a, b) \
    asm("fma.rn.f32x2 %0, %1, %2, %0;" : "+l"(acc) : "l"(a), "l"(b))

// ---------------------------------------------------------------------------
// Kernel 0: transpose W_in [H][I] -> g_winT [I][H]  (tiny, 256 KB)
// ---------------------------------------------------------------------------
__global__ void k0_transpose(const float* __restrict__ W_in) {
    int idx = blockIdx.x * blockDim.x + threadIdx.x;   // 0 .. I*H-1
    int h = idx & (RH - 1);
    int i = idx >> 9;           // idx / RH
    g_winT[i * RH + h] = W_in[h * RI + i];
}

// ---------------------------------------------------------------------------
// Kernel 1: x_proj[b][t][h] = sum_i inputs[b][t][i] * W_in[h][i]
// Tiled fp32 GEMM: CTA = 64 rows (b,t) x 128 h-cols, K = 128 (one pass).
// ---------------------------------------------------------------------------
#define K1_SMEM_BYTES ((64 * 128 + 128 * 132) * 4)

__global__ void k1_xproj(const float* __restrict__ inp) {
    extern __shared__ float sm[];
    float* As = sm;                  // [64][128]
    float* Ws = sm + 64 * 128;       // [128][132] (padded, k-major)
    const int row0 = blockIdx.x * 64;   // row in [B*T)
    const int hc   = blockIdx.y * 128;  // h col base
    const int tid  = threadIdx.x;

    for (int idx = tid; idx < 64 * 128; idx += 256)
        As[idx] = inp[(size_t)row0 * RI + idx];     // rows contiguous
    for (int idx = tid; idx < 128 * 128; idx += 256) {
        int i = idx >> 7, h = idx & 127;
        Ws[i * 132 + h] = g_winT[i * RH + hc + h];
    }
    __syncthreads();

    const int colg = tid & 31;     // 32 col groups (h = colg + 32*j)
    const int warp = tid >> 5;     // 8 row groups (r = warp + 8*jr)
    float acc[8][4];
#pragma unroll
    for (int a = 0; a < 8; a++)
#pragma unroll
        for (int b = 0; b < 4; b++) acc[a][b] = 0.f;

#pragma unroll 4
    for (int k = 0; k < 128; k++) {
        float w[4], a[8];
#pragma unroll
        for (int j = 0; j < 4; j++) w[j] = Ws[k * 132 + colg + 32 * j];
#pragma unroll
        for (int jr = 0; jr < 8; jr++) a[jr] = As[(warp + 8 * jr) * 128 + k];
#pragma unroll
        for (int jr = 0; jr < 8; jr++)
#pragma unroll
            for (int j = 0; j < 4; j++) acc[jr][j] += a[jr] * w[j];
    }

#pragma unroll
    for (int jr = 0; jr < 8; jr++)
#pragma unroll
        for (int j = 0; j < 4; j++)
            g_xproj[(size_t)(row0 + warp + 8 * jr) * RH + hc + colg + 32 * j] = acc[jr][j];
}

// ---------------------------------------------------------------------------
// Kernel 2: recurrent scan — dual-batch-group cluster, barrier.cluster/step.
// Grid: 64 CTAs = 8 clusters x 8 CTAs. Cluster c owns batch rows 8c..8c+7,
// as two groups G0 (rows +0..3) and G1 (rows +4..7). CTA rank r owns hidden
// cols [64r,64r+64); W register-resident (ulonglong2 wr[32], shared by both
// groups — that's the whole point: 2x compute per fixed per-step overhead).
//
// Per step (ONE syncthreads + ONE barrier.cluster for BOTH groups):
//   GEMM G0 -> red0 ; GEMM G1 -> red1   (disjoint buffers, no sync between)
//   __syncthreads
//   epi G0 on tid<64 || epi G1 on tid 64..127  (parallel warps):
//     reduce 16 k-slices, tanh.approx, leaky update, push float4 from
//     registers to all 8 CTAs' hb_g[nxt] (st.shared::cluster.v4), hh store.
//   barrier.cluster (release pushes / acquire for next step's GEMM reads;
//     also orders epi's red reads before next step's red writes).
// Single red buffer per group is safe: next write is after the barrier.
// No mbarriers -> no R8-style exit fault; loop's final barrier keeps the
// cluster quiescent before exit.
// ---------------------------------------------------------------------------
#define K2_WSTRIDE 72                      // floats per k-row of W staging (pad)
#define K2_HB0  (512 * K2_WSTRIDE)         // 36864: hb0[2][512][4]
#define K2_HB1  (K2_HB0 + 4096)            // 40960: hb1[2][512][4]
#define K2_RED0 (K2_HB1 + 4096)            // 45056: red0[16][4][64]
#define K2_RED1 (K2_RED0 + 4096)           // 49152: red1[16][4][64]
#define K2_BS   (K2_RED1 + 4096)           // 53248: bias[64]
#define K2_SMEM_FLOATS (K2_BS + 64)        // 53312
#define K2_SMEM_BYTES (K2_SMEM_FLOATS * 4) // 213248 B

__global__ void __launch_bounds__(256, 1)
k2_rnn(const float* __restrict__ hidden,
       const float* __restrict__ W_rec,
       const float* __restrict__ bvec) {
    extern __shared__ float sm[];
    float* Wl   = sm;                   // [512][72]   W staging (init only)
    float* hb0  = sm + K2_HB0;          // [2][512][4] G0 h, k-major, b minor
    float* hb1  = sm + K2_HB1;          // [2][512][4] G1 h
    float* red0 = sm + K2_RED0;         // [16][4][64] G0 partials
    float* red1 = sm + K2_RED1;         // [16][4][64] G1 partials
    float* bs   = sm + K2_BS;           // [64] bias slice

    const int tid  = threadIdx.x;
    const unsigned rank = blockIdx.x & 7;     // == %cluster_ctarank for (8,1,1)
    const int b0  = (blockIdx.x >> 3) * 8;    // batch base (8 rows per cluster)
    const int c0g = rank * 64;                // global col base for this CTA

    // Stage W_rec slice into SMEM, transposing to k-major (one-time)
    for (int idx = tid; idx < 64 * 512; idx += 256) {
        int c = idx >> 9, k = idx & 511;
        Wl[k * K2_WSTRIDE + c] = W_rec[(size_t)(c0g + c) * RH + k];
    }
    if (tid < 64) bs[tid] = bvec[c0g + tid];
    // Initial hidden -> slot 0 of both groups
    for (int idx = tid; idx < 4096; idx += 256) {
        int half = idx >> 11;          // 0: G0, 1: G1
        int j = idx & 2047;
        int b = j & 3, k = j >> 2;
        (half ? hb1 : hb0)[k * 4 + b] = hidden[(b0 + half * 4 + b) * RH + k];
    }
    __syncthreads();

    const int colg   = tid & 15;
    const int kslice = tid >> 4;
    const int kbase  = kslice * 32;

    // ---- pull this thread's W tile into registers (64 pairs = 128 regs) ----
    ulonglong2 wr[32];
#pragma unroll
    for (int kk = 0; kk < 32; kk++)
        wr[kk] = *reinterpret_cast<const ulonglong2*>(
            Wl + (kbase + kk) * K2_WSTRIDE + colg * 4);   // (w0,w1),(w2,w3)

    uint32_t smem_u32;
    asm("{ .reg .u64 t; cvta.to.shared.u64 t, %1; cvt.u32.u64 %0, t; }"
        : "=r"(smem_u32) : "l"(sm));
    const uint32_t hb0_base = smem_u32 + (uint32_t)(K2_HB0 * 4);
    uint32_t pb[8];      // hb0 base at each destination CTA
#pragma unroll
    for (int r = 0; r < 8; r++)
        asm("mapa.shared::cluster.u32 %0, %1, %2;" : "=r"(pb[r]) : "r"(hb0_base), "r"(r));

    // Epilogue (tid<128): group eg = tid>>6, one col x 4 batch rows
    const int eg  = (tid >> 6) & 1;
    const int uc  = tid & 63;
    const int gcu = c0g + uc;
    const float bias = bs[uc];
    const float* xp_p = g_xproj + (size_t)(b0 + 4 * eg) * RT * RH + gcu;
    float*       hh_p = g_hhist + (size_t)(b0 + 4 * eg) * RT * RH + gcu;
    const uint32_t grpoff = (uint32_t)(eg * 16384);   // hb1 is +16384 B after hb0
    const uint32_t choff  = (uint32_t)(gcu * 16);     // byte offset of col's float4
    float* myhb  = eg ? hb1 : hb0;
    const float* myred = eg ? red1 : red0;

    float4* red04 = reinterpret_cast<float4*>(red0);
    float4* red14 = reinterpret_cast<float4*>(red1);

    // Initial hb visible cluster-wide before any remote push targets us
    asm volatile("barrier.cluster.arrive.aligned;" ::: "memory");
    asm volatile("barrier.cluster.wait.aligned;"   ::: "memory");

    for (int t = 0; t < RT; t++) {
        const int par = t & 1;

        // Prefetch xp for the epilogue (independent of h — issue before GEMM)
        float xp0, xp1, xp2, xp3;
        if (tid < 128) {
            const size_t o = (size_t)t * RH;
            xp0 = __ldg(xp_p + o);
            xp1 = __ldg(xp_p + (size_t)RT * RH + o);
            xp2 = __ldg(xp_p + 2 * (size_t)RT * RH + o);
            xp3 = __ldg(xp_p + 3 * (size_t)RT * RH + o);
        }

        // ---- GEMM G0 ----
        {
            const float4* h4 = reinterpret_cast<const float4*>(hb0 + par * 2048 + kbase * 4);
            uint64_t a0p0 = 0, a0p1 = 0, a1p0 = 0, a1p1 = 0;
            uint64_t a2p0 = 0, a2p1 = 0, a3p0 = 0, a3p1 = 0;
#pragma unroll
            for (int kk = 0; kk < 32; kk++) {
                const float4 hv = h4[kk];          // broadcast LDS.128
                uint64_t hd0, hd1, hd2, hd3;
                PK2(hd0, hv.x, hv.x);
                PK2(hd1, hv.y, hv.y);
                PK2(hd2, hv.z, hv.z);
                PK2(hd3, hv.w, hv.w);
                FMA2(a0p0, hd0, wr[kk].x); FMA2(a0p1, hd0, wr[kk].y);
                FMA2(a1p0, hd1, wr[kk].x); FMA2(a1p1, hd1, wr[kk].y);
                FMA2(a2p0, hd2, wr[kk].x); FMA2(a2p1, hd2, wr[kk].y);
                FMA2(a3p0, hd3, wr[kk].x); FMA2(a3p1, hd3, wr[kk].y);
            }
            float4* rp = red04 + kslice * 64;
            float4 f;
            UPK2(f.x, f.y, a0p0); UPK2(f.z, f.w, a0p1); rp[0 * 16 + colg] = f;
            UPK2(f.x, f.y, a1p0); UPK2(f.z, f.w, a1p1); rp[1 * 16 + colg] = f;
            UPK2(f.x, f.y, a2p0); UPK2(f.z, f.w, a2p1); rp[2 * 16 + colg] = f;
            UPK2(f.x, f.y, a3p0); UPK2(f.z, f.w, a3p1); rp[3 * 16 + colg] = f;
        }
        // ---- GEMM G1 ----
        {
            const float4* h4 = reinterpret_cast<const float4*>(hb1 + par * 2048 + kbase * 4);
            uint64_t a0p0 = 0, a0p1 = 0, a1p0 = 0, a1p1 = 0;
            uint64_t a2p0 = 0, a2p1 = 0, a3p0 = 0, a3p1 = 0;
#pragma unroll
            for (int kk = 0; kk < 32; kk++) {
                const float4 hv = h4[kk];
                uint64_t hd0, hd1, hd2, hd3;
                PK2(hd0, hv.x, hv.x);
                PK2(hd1, hv.y, hv.y);
                PK2(hd2, hv.z, hv.z);
                PK2(hd3, hv.w, hv.w);
                FMA2(a0p0, hd0, wr[kk].x); FMA2(a0p1, hd0, wr[kk].y);
                FMA2(a1p0, hd1, wr[kk].x); FMA2(a1p1, hd1, wr[kk].y);
                FMA2(a2p0, hd2, wr[kk].x); FMA2(a2p1, hd2, wr[kk].y);
                FMA2(a3p0, hd3, wr[kk].x); FMA2(a3p1, hd3, wr[kk].y);
            }
            float4* rp = red14 + kslice * 64;
            float4 f;
            UPK2(f.x, f.y, a0p0); UPK2(f.z, f.w, a0p1); rp[0 * 16 + colg] = f;
            UPK2(f.x, f.y, a1p0); UPK2(f.z, f.w, a1p1); rp[1 * 16 + colg] = f;
            UPK2(f.x, f.y, a2p0); UPK2(f.z, f.w, a2p1); rp[2 * 16 + colg] = f;
            UPK2(f.x, f.y, a3p0); UPK2(f.z, f.w, a3p1); rp[3 * 16 + colg] = f;
        }

        __syncthreads();   // both groups' partials visible to epilogues

        // ---- Parallel epilogues: tid<64 -> G0, tid 64..127 -> G1 ----
        if (tid < 128) {
            float s0 = 0.f, s1 = 0.f, s2 = 0.f, s3 = 0.f;
#pragma unroll
            for (int ss = 0; ss < 16; ss++) {
                const float* q = myred + ss * 256 + uc;
                s0 += q[0];
                s1 += q[64];
                s2 += q[128];
                s3 += q[192];
            }
            float t0, t1, t2, t3;
            asm("tanh.approx.f32 %0, %1;" : "=f"(t0) : "f"(s0 + xp0 + bias));
            asm("tanh.approx.f32 %0, %1;" : "=f"(t1) : "f"(s1 + xp1 + bias));
            asm("tanh.approx.f32 %0, %1;" : "=f"(t2) : "f"(s2 + xp2 + bias));
            asm("tanh.approx.f32 %0, %1;" : "=f"(t3) : "f"(s3 + xp3 + bias));
            const float4 hold = *reinterpret_cast<const float4*>(myhb + par * 2048 + gcu * 4);
            float4 v;
            v.x = 0.9f * hold.x + 0.1f * t0;
            v.y = 0.9f * hold.y + 0.1f * t1;
            v.z = 0.9f * hold.z + 0.1f * t2;
            v.w = 0.9f * hold.w + 0.1f * t3;

            if (t < RT - 1) {
                // Push h(t) into slot (t+1)&1 at all 8 CTAs (incl. self)
                const uint32_t doff = grpoff + (uint32_t)((par ^ 1) * 8192) + choff;
#pragma unroll
                for (int r = 0; r < 8; r++)
                    asm volatile("st.shared::cluster.v4.f32 [%0], {%1,%2,%3,%4};"
                                 :: "r"(pb[r] + doff),
                                    "f"(v.x), "f"(v.y), "f"(v.z), "f"(v.w) : "memory");
            }

            // Persist h(t) for the output pass (off the critical path)
            const size_t o = (size_t)t * RH;
            hh_p[o]                       = v.x;
            hh_p[(size_t)RT * RH + o]     = v.y;
            hh_p[2 * (size_t)RT * RH + o] = v.z;
            hh_p[3 * (size_t)RT * RH + o] = v.w;
        }

        // ---- One cluster barrier per step: releases pushes, orders red
        //      reads before next step's writes, acquires remote h for t+1 ----
        asm volatile("barrier.cluster.arrive.aligned;" ::: "memory");
        asm volatile("barrier.cluster.wait.aligned;"   ::: "memory");
    }
}

// ---------------------------------------------------------------------------
// Kernel 3: out[b][t][o] = sum_h hhist[b][t][h] * W_out[o][h] + b_out[o]
// CTA = 128 rows x 32 o-cols; SMEM ~99 KB -> 2 CTAs/SM, 512 CTAs.
// ---------------------------------------------------------------------------
#define K3_WS 513
#define K3_AS 65
#define K3_SMEM_BYTES ((32 * K3_WS + 128 * K3_AS) * 4)

__global__ void k3_out(const float* __restrict__ W_out,
                       const float* __restrict__ b_out,
                       float* __restrict__ out) {
    extern __shared__ float sm[];
    float* Ws = sm;                   // [32][513]
    float* As = sm + 32 * K3_WS;      // [128][65]
    const int row0 = blockIdx.x * 128;
    const int ob0  = blockIdx.y * 32;  // o col base
    const int tid  = threadIdx.x;

    for (int idx = tid; idx < 32 * 512; idx += 256) {
        int o = idx >> 9, k = idx & 511;
        Ws[o * K3_WS + k] = W_out[(size_t)(ob0 + o) * RH + k];
    }

    const int og   = tid & 15;    // o = og + 16*j, j<2
    const int rowg = tid >> 4;    // r = rowg + 16*jr, jr<8
    float acc[8][2];
#pragma unroll
    for (int a = 0; a < 8; a++) { acc[a][0] = 0.f; acc[a][1] = 0.f; }

    for (int kc = 0; kc < 8; kc++) {
        __syncthreads();
        for (int idx = tid; idx < 128 * 64; idx += 256) {
            int r = idx >> 6, k = idx & 63;
            As[r * K3_AS + k] = g_hhist[(size_t)(row0 + r) * RH + kc * 64 + k];
        }
        __syncthreads();
#pragma unroll 4
        for (int kk = 0; kk < 64; kk++) {
            const int k = kc * 64 + kk;
            float w[2], a[8];
#pragma unroll
            for (int j = 0; j < 2; j++) w[j] = Ws[(og + 16 * j) * K3_WS + k];
#pragma unroll
            for (int jr = 0; jr < 8; jr++) a[jr] = As[(rowg + 16 * jr) * K3_AS + kk];
#pragma unroll
            for (int jr = 0; jr < 8; jr++)
#pragma unroll
                for (int j = 0; j < 2; j++) acc[jr][j] += a[jr] * w[j];
        }
    }

#pragma unroll
    for (int jr = 0; jr < 8; jr++)
#pragma unroll
        for (int j = 0; j < 2; j++)
            out[(size_t)(row0 + rowg + 16 * jr) * RO + ob0 + og + 16 * j] =
                acc[jr][j] + __ldg(&b_out[ob0 + og + 16 * j]);
}

// ---------------------------------------------------------------------------
// Kernel 4: h_final[b][h] = hhist[b][T-1][h]
// ---------------------------------------------------------------------------
__global__ void k4_hfinal(float* __restrict__ outh) {
    int idx = blockIdx.x * blockDim.x + threadIdx.x;   // 0 .. B*H-1
    int b = idx >> 9, h = idx & 511;
    outh[idx] = g_hhist[(size_t)b * RT * RH + (size_t)(RT - 1) * RH + h];
}

// ---------------------------------------------------------------------------
// Launch
// ---------------------------------------------------------------------------
extern "C" void kernel_launch(void* const* d_in, const int* in_sizes, int n_in,
                              void* d_out, int out_size) {
    const float* inputs = (const float*)d_in[0];
    const float* hidden = (const float*)d_in[1];
    const float* W_in   = (const float*)d_in[2];
    const float* W_rec  = (const float*)d_in[3];
    const float* bvec   = (const float*)d_in[4];
    const float* W_out  = (const float*)d_in[5];
    const float* b_out  = (const float*)d_in[6];
    float* out = (float*)d_out;

    cudaFuncSetAttribute(k1_xproj, cudaFuncAttributeMaxDynamicSharedMemorySize, K1_SMEM_BYTES);
    cudaFuncSetAttribute(k2_rnn,   cudaFuncAttributeMaxDynamicSharedMemorySize, K2_SMEM_BYTES);
    cudaFuncSetAttribute(k3_out,   cudaFuncAttributeMaxDynamicSharedMemorySize, K3_SMEM_BYTES);

    k0_transpose<<<(RI * RH) / 256, 256>>>(W_in);
    k1_xproj<<<dim3((RB * RT) / 64, RH / 128), 256, K1_SMEM_BYTES>>>(inputs);

    cudaLaunchConfig_t cfg = {};
    cfg.gridDim  = dim3(64, 1, 1);            // 8 clusters x 8 CTAs
    cfg.blockDim = dim3(256, 1, 1);
    cfg.dynamicSmemBytes = K2_SMEM_BYTES;
    cfg.stream = 0;
    cudaLaunchAttribute attrs[1];
    attrs[0].id = cudaLaunchAttributeClusterDimension;
    attrs[0].val.clusterDim.x = 8;
    attrs[0].val.clusterDim.y = 1;
    attrs[0].val.clusterDim.z = 1;
    cfg.attrs = attrs;
    cfg.numAttrs = 1;
    cudaLaunchKernelEx(&cfg, k2_rnn, hidden, W_rec, bvec);

    k3_out<<<dim3((RB * RT) / 128, RO / 32), 256, K3_SMEM_BYTES>>>(W_out, b_out, out);

    if (out_size >= RB * RT * RO + RB * RH)
        k4_hfinal<<<(RB * RH) / 256, 256>>>(out + (size_t)RB * RT * RO);
}

// round 15
// speedup vs baseline: 2.4706x; 1.0327x over previous
#include <cuda_runtime.h>
#include <cstdint>

// Problem dims (fixed by the dataset problem)
#define RB 64      // batch
#define RT 512     // time steps
#define RI 128     // input dim
#define RH 512     // hidden dim
#define RO 64      // output dim

// ---------------------------------------------------------------------------
// Device scratch (allocation-free rule: __device__ globals)
// ---------------------------------------------------------------------------
__device__ float g_winT[RI * RH];                // W_in transposed: [I][H]
__device__ float g_xproj[(size_t)RB * RT * RH];  // [B][T][H] input projections
__device__ float g_hhist[(size_t)RB * RT * RH];  // [B][T][H] hidden states

// Packed fp32x2 helpers (Blackwell FFMA2 — ptxas never emits this from C++)
#define PK2(dst, lo, hi) \
    asm("mov.b64 %0, {%1, %2};" : "=l"(dst) : "f"(lo), "f"(hi))
#define UPK2(lo, hi, src) \
    asm("mov.b64 {%0, %1}, %2;" : "=f"(lo), "=f"(hi) : "l"(src))
#define FMA2(acc, a, b) \
    asm("fma.rn.f32x2 %0, %1, %2, %0;" : "+l"(acc) : "l"(a), "l"(b))

// ---------------------------------------------------------------------------
// Kernel 0: transpose W_in [H][I] -> g_winT [I][H]  (tiny, 256 KB)
// ---------------------------------------------------------------------------
__global__ void k0_transpose(const float* __restrict__ W_in) {
    int idx = blockIdx.x * blockDim.x + threadIdx.x;   // 0 .. I*H-1
    int h = idx & (RH - 1);
    int i = idx >> 9;           // idx / RH
    g_winT[i * RH + h] = W_in[h * RI + i];
}

// ---------------------------------------------------------------------------
// Kernel 1: x_proj[b][t][h] = sum_i inputs[b][t][i] * W_in[h][i]
// Tiled fp32 GEMM: CTA = 64 rows (b,t) x 128 h-cols, K = 128 (one pass).
// ---------------------------------------------------------------------------
#define K1_SMEM_BYTES ((64 * 128 + 128 * 132) * 4)

__global__ void k1_xproj(const float* __restrict__ inp) {
    extern __shared__ float sm[];
    float* As = sm;                  // [64][128]
    float* Ws = sm + 64 * 128;       // [128][132] (padded, k-major)
    const int row0 = blockIdx.x * 64;   // row in [B*T)
    const int hc   = blockIdx.y * 128;  // h col base
    const int tid  = threadIdx.x;

    for (int idx = tid; idx < 64 * 128; idx += 256)
        As[idx] = inp[(size_t)row0 * RI + idx];     // rows contiguous
    for (int idx = tid; idx < 128 * 128; idx += 256) {
        int i = idx >> 7, h = idx & 127;
        Ws[i * 132 + h] = g_winT[i * RH + hc + h];
    }
    __syncthreads();

    const int colg = tid & 31;     // 32 col groups (h = colg + 32*j)
    const int warp = tid >> 5;     // 8 row groups (r = warp + 8*jr)
    float acc[8][4];
#pragma unroll
    for (int a = 0; a < 8; a++)
#pragma unroll
        for (int b = 0; b < 4; b++) acc[a][b] = 0.f;

#pragma unroll 4
    for (int k = 0; k < 128; k++) {
        float w[4], a[8];
#pragma unroll
        for (int j = 0; j < 4; j++) w[j] = Ws[k * 132 + colg + 32 * j];
#pragma unroll
        for (int jr = 0; jr < 8; jr++) a[jr] = As[(warp + 8 * jr) * 128 + k];
#pragma unroll
        for (int jr = 0; jr < 8; jr++)
#pragma unroll
            for (int j = 0; j < 4; j++) acc[jr][j] += a[jr] * w[j];
    }

#pragma unroll
    for (int jr = 0; jr < 8; jr++)
#pragma unroll
        for (int j = 0; j < 4; j++)
            g_xproj[(size_t)(row0 + warp + 8 * jr) * RH + hc + colg + 32 * j] = acc[jr][j];
}

// ---------------------------------------------------------------------------
// Kernel 2: recurrent scan — dual-batch-group cluster (the R14 winner) with
// an arrive/wait-split barrier: hh global stores and next-step xp prefetch
// ride inside the cluster-rendezvous window instead of extending the step.
// Grid: 64 CTAs = 8 clusters x 8 CTAs; 8 batch rows per cluster (G0/G1).
// ---------------------------------------------------------------------------
#define K2_WSTRIDE 72                      // floats per k-row of W staging (pad)
#define K2_HB0  (512 * K2_WSTRIDE)         // 36864: hb0[2][512][4]
#define K2_HB1  (K2_HB0 + 4096)            // 40960: hb1[2][512][4]
#define K2_RED0 (K2_HB1 + 4096)            // 45056: red0[16][4][64]
#define K2_RED1 (K2_RED0 + 4096)           // 49152: red1[16][4][64]
#define K2_BS   (K2_RED1 + 4096)           // 53248: bias[64]
#define K2_SMEM_FLOATS (K2_BS + 64)        // 53312
#define K2_SMEM_BYTES (K2_SMEM_FLOATS * 4) // 213248 B

__global__ void __launch_bounds__(256, 1)
k2_rnn(const float* __restrict__ hidden,
       const float* __restrict__ W_rec,
       const float* __restrict__ bvec) {
    extern __shared__ float sm[];
    float* Wl   = sm;                   // [512][72]   W staging (init only)
    float* hb0  = sm + K2_HB0;          // [2][512][4] G0 h, k-major, b minor
    float* hb1  = sm + K2_HB1;          // [2][512][4] G1 h
    float* red0 = sm + K2_RED0;         // [16][4][64] G0 partials
    float* red1 = sm + K2_RED1;         // [16][4][64] G1 partials
    float* bs   = sm + K2_BS;           // [64] bias slice

    const int tid  = threadIdx.x;
    const unsigned rank = blockIdx.x & 7;     // == %cluster_ctarank for (8,1,1)
    const int b0  = (blockIdx.x >> 3) * 8;    // batch base (8 rows per cluster)
    const int c0g = rank * 64;                // global col base for this CTA

    // Stage W_rec slice into SMEM, transposing to k-major (one-time)
    for (int idx = tid; idx < 64 * 512; idx += 256) {
        int c = idx >> 9, k = idx & 511;
        Wl[k * K2_WSTRIDE + c] = W_rec[(size_t)(c0g + c) * RH + k];
    }
    if (tid < 64) bs[tid] = bvec[c0g + tid];
    // Initial hidden -> slot 0 of both groups
    for (int idx = tid; idx < 4096; idx += 256) {
        int half = idx >> 11;          // 0: G0, 1: G1
        int j = idx & 2047;
        int b = j & 3, k = j >> 2;
        (half ? hb1 : hb0)[k * 4 + b] = hidden[(b0 + half * 4 + b) * RH + k];
    }
    __syncthreads();

    const int colg   = tid & 15;
    const int kslice = tid >> 4;
    const int kbase  = kslice * 32;

    // ---- pull this thread's W tile into registers (64 pairs = 128 regs) ----
    ulonglong2 wr[32];
#pragma unroll
    for (int kk = 0; kk < 32; kk++)
        wr[kk] = *reinterpret_cast<const ulonglong2*>(
            Wl + (kbase + kk) * K2_WSTRIDE + colg * 4);   // (w0,w1),(w2,w3)

    uint32_t smem_u32;
    asm("{ .reg .u64 t; cvta.to.shared.u64 t, %1; cvt.u32.u64 %0, t; }"
        : "=r"(smem_u32) : "l"(sm));
    const uint32_t hb0_base = smem_u32 + (uint32_t)(K2_HB0 * 4);
    uint32_t pb[8];      // hb0 base at each destination CTA
#pragma unroll
    for (int r = 0; r < 8; r++)
        asm("mapa.shared::cluster.u32 %0, %1, %2;" : "=r"(pb[r]) : "r"(hb0_base), "r"(r));

    // Epilogue (tid<128): group eg = tid>>6, one col x 4 batch rows
    const int eg  = (tid >> 6) & 1;
    const int uc  = tid & 63;
    const int gcu = c0g + uc;
    const float bias = bs[uc];
    const float* xp_p = g_xproj + (size_t)(b0 + 4 * eg) * RT * RH + gcu;
    float*       hh_p = g_hhist + (size_t)(b0 + 4 * eg) * RT * RH + gcu;
    const uint32_t grpoff = (uint32_t)(eg * 16384);   // hb1 is +16384 B after hb0
    const uint32_t choff  = (uint32_t)(gcu * 16);     // byte offset of col's float4
    float* myhb  = eg ? hb1 : hb0;
    const float* myred = eg ? red1 : red0;

    float4* red04 = reinterpret_cast<float4*>(red0);
    float4* red14 = reinterpret_cast<float4*>(red1);

    // Initial hb visible cluster-wide before any remote push targets us
    asm volatile("barrier.cluster.arrive.aligned;" ::: "memory");
    asm volatile("barrier.cluster.wait.aligned;"   ::: "memory");

    // Prefetch xp(0) (epilogue threads only)
    float xp0 = 0.f, xp1 = 0.f, xp2 = 0.f, xp3 = 0.f;
    if (tid < 128) {
        xp0 = __ldg(xp_p);
        xp1 = __ldg(xp_p + (size_t)RT * RH);
        xp2 = __ldg(xp_p + 2 * (size_t)RT * RH);
        xp3 = __ldg(xp_p + 3 * (size_t)RT * RH);
    }

    for (int t = 0; t < RT; t++) {
        const int par = t & 1;

        // ---- GEMM G0 ----
        {
            const float4* h4 = reinterpret_cast<const float4*>(hb0 + par * 2048 + kbase * 4);
            uint64_t a0p0 = 0, a0p1 = 0, a1p0 = 0, a1p1 = 0;
            uint64_t a2p0 = 0, a2p1 = 0, a3p0 = 0, a3p1 = 0;
#pragma unroll
            for (int kk = 0; kk < 32; kk++) {
                const float4 hv = h4[kk];          // broadcast LDS.128
                uint64_t hd0, hd1, hd2, hd3;
                PK2(hd0, hv.x, hv.x);
                PK2(hd1, hv.y, hv.y);
                PK2(hd2, hv.z, hv.z);
                PK2(hd3, hv.w, hv.w);
                FMA2(a0p0, hd0, wr[kk].x); FMA2(a0p1, hd0, wr[kk].y);
                FMA2(a1p0, hd1, wr[kk].x); FMA2(a1p1, hd1, wr[kk].y);
                FMA2(a2p0, hd2, wr[kk].x); FMA2(a2p1, hd2, wr[kk].y);
                FMA2(a3p0, hd3, wr[kk].x); FMA2(a3p1, hd3, wr[kk].y);
            }
            float4* rp = red04 + kslice * 64;
            float4 f;
            UPK2(f.x, f.y, a0p0); UPK2(f.z, f.w, a0p1); rp[0 * 16 + colg] = f;
            UPK2(f.x, f.y, a1p0); UPK2(f.z, f.w, a1p1); rp[1 * 16 + colg] = f;
            UPK2(f.x, f.y, a2p0); UPK2(f.z, f.w, a2p1); rp[2 * 16 + colg] = f;
            UPK2(f.x, f.y, a3p0); UPK2(f.z, f.w, a3p1); rp[3 * 16 + colg] = f;
        }
        // ---- GEMM G1 ----
        {
            const float4* h4 = reinterpret_cast<const float4*>(hb1 + par * 2048 + kbase * 4);
            uint64_t a0p0 = 0, a0p1 = 0, a1p0 = 0, a1p1 = 0;
            uint64_t a2p0 = 0, a2p1 = 0, a3p0 = 0, a3p1 = 0;
#pragma unroll
            for (int kk = 0; kk < 32; kk++) {
                const float4 hv = h4[kk];
                uint64_t hd0, hd1, hd2, hd3;
                PK2(hd0, hv.x, hv.x);
                PK2(hd1, hv.y, hv.y);
                PK2(hd2, hv.z, hv.z);
                PK2(hd3, hv.w, hv.w);
                FMA2(a0p0, hd0, wr[kk].x); FMA2(a0p1, hd0, wr[kk].y);
                FMA2(a1p0, hd1, wr[kk].x); FMA2(a1p1, hd1, wr[kk].y);
                FMA2(a2p0, hd2, wr[kk].x); FMA2(a2p1, hd2, wr[kk].y);
                FMA2(a3p0, hd3, wr[kk].x); FMA2(a3p1, hd3, wr[kk].y);
            }
            float4* rp = red14 + kslice * 64;
            float4 f;
            UPK2(f.x, f.y, a0p0); UPK2(f.z, f.w, a0p1); rp[0 * 16 + colg] = f;
            UPK2(f.x, f.y, a1p0); UPK2(f.z, f.w, a1p1); rp[1 * 16 + colg] = f;
            UPK2(f.x, f.y, a2p0); UPK2(f.z, f.w, a2p1); rp[2 * 16 + colg] = f;
            UPK2(f.x, f.y, a3p0); UPK2(f.z, f.w, a3p1); rp[3 * 16 + colg] = f;
        }

        __syncthreads();   // both groups' partials visible to epilogues

        // ---- Parallel epilogues: tid<64 -> G0, tid 64..127 -> G1 ----
        float4 v;
        if (tid < 128) {
            float s0 = 0.f, s1 = 0.f, s2 = 0.f, s3 = 0.f;
#pragma unroll
            for (int ss = 0; ss < 16; ss++) {
                const float* q = myred + ss * 256 + uc;
                s0 += q[0];
                s1 += q[64];
                s2 += q[128];
                s3 += q[192];
            }
            float t0, t1, t2, t3;
            asm("tanh.approx.f32 %0, %1;" : "=f"(t0) : "f"(s0 + xp0 + bias));
            asm("tanh.approx.f32 %0, %1;" : "=f"(t1) : "f"(s1 + xp1 + bias));
            asm("tanh.approx.f32 %0, %1;" : "=f"(t2) : "f"(s2 + xp2 + bias));
            asm("tanh.approx.f32 %0, %1;" : "=f"(t3) : "f"(s3 + xp3 + bias));
            const float4 hold = *reinterpret_cast<const float4*>(myhb + par * 2048 + gcu * 4);
            v.x = 0.9f * hold.x + 0.1f * t0;
            v.y = 0.9f * hold.y + 0.1f * t1;
            v.z = 0.9f * hold.z + 0.1f * t2;
            v.w = 0.9f * hold.w + 0.1f * t3;

            if (t < RT - 1) {
                // Push h(t) into slot (t+1)&1 at all 8 CTAs (incl. self)
                const uint32_t doff = grpoff + (uint32_t)((par ^ 1) * 8192) + choff;
#pragma unroll
                for (int r = 0; r < 8; r++)
                    asm volatile("st.shared::cluster.v4.f32 [%0], {%1,%2,%3,%4};"
                                 :: "r"(pb[r] + doff),
                                    "f"(v.x), "f"(v.y), "f"(v.z), "f"(v.w) : "memory");
            }
        }

        // ---- Arrive (releases pushes + orders red reads), then hide global
        //      traffic inside the rendezvous window, then wait ----
        asm volatile("barrier.cluster.arrive.aligned;" ::: "memory");

        if (tid < 128) {
            // Persist h(t) — global, no cluster ordering needed
            const size_t o = (size_t)t * RH;
            hh_p[o]                       = v.x;
            hh_p[(size_t)RT * RH + o]     = v.y;
            hh_p[2 * (size_t)RT * RH + o] = v.z;
            hh_p[3 * (size_t)RT * RH + o] = v.w;
            // Prefetch xp(t+1)
            if (t + 1 < RT) {
                const size_t o2 = (size_t)(t + 1) * RH;
                xp0 = __ldg(xp_p + o2);
                xp1 = __ldg(xp_p + (size_t)RT * RH + o2);
                xp2 = __ldg(xp_p + 2 * (size_t)RT * RH + o2);
                xp3 = __ldg(xp_p + 3 * (size_t)RT * RH + o2);
            }
        }

        asm volatile("barrier.cluster.wait.aligned;" ::: "memory");
    }
}

// ---------------------------------------------------------------------------
// Kernel 3: out[b][t][o] = sum_h hhist[b][t][h] * W_out[o][h] + b_out[o]
// CTA = 128 rows x 32 o-cols, k chunked by 64 for BOTH As and Ws:
// SMEM ~42 KB -> 5 CTAs/SM (62% occ), vs 99 KB / 2 CTAs before.
// ---------------------------------------------------------------------------
#define K3_CH 64
#define K3_WP 66                           // padded chunk stride
#define K3_SMEM_BYTES ((32 * K3_WP + 128 * K3_WP) * 4)   // 42240 B

__global__ void k3_out(const float* __restrict__ W_out,
                       const float* __restrict__ b_out,
                       float* __restrict__ out) {
    extern __shared__ float sm[];
    float* Ws = sm;                    // [32][66] current k-chunk of W
    float* As = sm + 32 * K3_WP;       // [128][66] current k-chunk of hhist
    const int row0 = blockIdx.x * 128;
    const int ob0  = blockIdx.y * 32;  // o col base
    const int tid  = threadIdx.x;

    const int og   = tid & 15;    // o = og + 16*j, j<2
    const int rowg = tid >> 4;    // r = rowg + 16*jr, jr<8
    float acc[8][2];
#pragma unroll
    for (int a = 0; a < 8; a++) { acc[a][0] = 0.f; acc[a][1] = 0.f; }

    for (int kc = 0; kc < 8; kc++) {
        __syncthreads();
        // Load W chunk: [32 o][64 k], coalesced over k
        for (int idx = tid; idx < 32 * K3_CH; idx += 256) {
            int o = idx >> 6, k = idx & 63;
            Ws[o * K3_WP + k] = W_out[(size_t)(ob0 + o) * RH + kc * K3_CH + k];
        }
        // Load A chunk: [128 r][64 k], coalesced over k
        for (int idx = tid; idx < 128 * K3_CH; idx += 256) {
            int r = idx >> 6, k = idx & 63;
            As[r * K3_WP + k] = g_hhist[(size_t)(row0 + r) * RH + kc * K3_CH + k];
        }
        __syncthreads();
#pragma unroll 4
        for (int kk = 0; kk < K3_CH; kk++) {
            float w[2], a[8];
#pragma unroll
            for (int j = 0; j < 2; j++) w[j] = Ws[(og + 16 * j) * K3_WP + kk];
#pragma unroll
            for (int jr = 0; jr < 8; jr++) a[jr] = As[(rowg + 16 * jr) * K3_WP + kk];
#pragma unroll
            for (int jr = 0; jr < 8; jr++)
#pragma unroll
                for (int j = 0; j < 2; j++) acc[jr][j] += a[jr] * w[j];
        }
    }

#pragma unroll
    for (int jr = 0; jr < 8; jr++)
#pragma unroll
        for (int j = 0; j < 2; j++)
            out[(size_t)(row0 + rowg + 16 * jr) * RO + ob0 + og + 16 * j] =
                acc[jr][j] + __ldg(&b_out[ob0 + og + 16 * j]);
}

// ---------------------------------------------------------------------------
// Kernel 4: h_final[b][h] = hhist[b][T-1][h]
// ---------------------------------------------------------------------------
__global__ void k4_hfinal(float* __restrict__ outh) {
    int idx = blockIdx.x * blockDim.x + threadIdx.x;   // 0 .. B*H-1
    int b = idx >> 9, h = idx & 511;
    outh[idx] = g_hhist[(size_t)b * RT * RH + (size_t)(RT - 1) * RH + h];
}

// ---------------------------------------------------------------------------
// Launch
// ---------------------------------------------------------------------------
extern "C" void kernel_launch(void* const* d_in, const int* in_sizes, int n_in,
                              void* d_out, int out_size) {
    const float* inputs = (const float*)d_in[0];
    const float* hidden = (const float*)d_in[1];
    const float* W_in   = (const float*)d_in[2];
    const float* W_rec  = (const float*)d_in[3];
    const float* bvec   = (const float*)d_in[4];
    const float* W_out  = (const float*)d_in[5];
    const float* b_out  = (const float*)d_in[6];
    float* out = (float*)d_out;

    cudaFuncSetAttribute(k1_xproj, cudaFuncAttributeMaxDynamicSharedMemorySize, K1_SMEM_BYTES);
    cudaFuncSetAttribute(k2_rnn,   cudaFuncAttributeMaxDynamicSharedMemorySize, K2_SMEM_BYTES);
    cudaFuncSetAttribute(k3_out,   cudaFuncAttributeMaxDynamicSharedMemorySize, K3_SMEM_BYTES);

    k0_transpose<<<(RI * RH) / 256, 256>>>(W_in);
    k1_xproj<<<dim3((RB * RT) / 64, RH / 128), 256, K1_SMEM_BYTES>>>(inputs);

    cudaLaunchConfig_t cfg = {};
    cfg.gridDim  = dim3(64, 1, 1);            // 8 clusters x 8 CTAs
    cfg.blockDim = dim3(256, 1, 1);
    cfg.dynamicSmemBytes = K2_SMEM_BYTES;
    cfg.stream = 0;
    cudaLaunchAttribute attrs[1];
    attrs[0].id = cudaLaunchAttributeClusterDimension;
    attrs[0].val.clusterDim.x = 8;
    attrs[0].val.clusterDim.y = 1;
    attrs[0].val.clusterDim.z = 1;
    cfg.attrs = attrs;
    cfg.numAttrs = 1;
    cudaLaunchKernelEx(&cfg, k2_rnn, hidden, W_rec, bvec);

    k3_out<<<dim3((RB * RT) / 128, RO / 32), 256, K3_SMEM_BYTES>>>(W_out, b_out, out);

    if (out_size >= RB * RT * RO + RB * RH)
        k4_hfinal<<<(RB * RH) / 256, 256>>>(out + (size_t)RB * RT * RO);
}